// round 2
// baseline (speedup 1.0000x reference)
#include <cuda_runtime.h>
#include <cuda_bf16.h>

#define FEAT 64
#define MAX_USERS 200000
#define MAX_SPOTS 50000
#define MAX_EDGES 3200000

// ---- device scratch (no allocations allowed) ------------------------------
__device__ int   g_udeg[MAX_USERS];
__device__ int   g_sdeg[MAX_SPOTS];
__device__ int   g_uoff[MAX_USERS + 1];
__device__ int   g_soff[MAX_SPOTS + 1];
__device__ int   g_ucur[MAX_USERS];
__device__ int   g_scur[MAX_SPOTS];
__device__ float g_uinv[MAX_USERS];
__device__ float g_sinv[MAX_SPOTS];
__device__ int   g_uadj[MAX_EDGES];   // per-user list of spot neighbors
__device__ int   g_sadj[MAX_EDGES];   // per-spot list of user neighbors

// ---------------------------------------------------------------------------
// K1: zero the integer degree arrays.
// ---------------------------------------------------------------------------
__global__ void zero_deg_kernel(int* __restrict__ udeg, int nu,
                                int* __restrict__ sdeg, int ns) {
    int stride = gridDim.x * blockDim.x;
    for (int i = blockIdx.x * blockDim.x + threadIdx.x; i < nu; i += stride)
        udeg[i] = 0;
    for (int i = blockIdx.x * blockDim.x + threadIdx.x; i < ns; i += stride)
        sdeg[i] = 0;
}

// ---------------------------------------------------------------------------
// K2: integer degree counts.
// ---------------------------------------------------------------------------
__global__ void degree_kernel(const int* __restrict__ user_idx,
                              const int* __restrict__ spot_idx,
                              int n_edges,
                              int* __restrict__ udeg,
                              int* __restrict__ sdeg) {
    int stride = gridDim.x * blockDim.x;
    for (int e = blockIdx.x * blockDim.x + threadIdx.x; e < n_edges; e += stride) {
        atomicAdd(&udeg[user_idx[e]], 1);
        atomicAdd(&sdeg[spot_idx[e]], 1);
    }
}

// ---------------------------------------------------------------------------
// K3: exclusive scan of degrees -> offsets (+cursors) and inv_sqrt weights.
// Two independent scans: block 0 = users, block 1 = spots. 1024 threads each.
// ---------------------------------------------------------------------------
__global__ void scan_kernel(const int* __restrict__ udeg, int nu,
                            int* __restrict__ uoff, int* __restrict__ ucur,
                            float* __restrict__ uinv,
                            const int* __restrict__ sdeg, int ns,
                            int* __restrict__ soff, int* __restrict__ scur,
                            float* __restrict__ sinv) {
    const int* deg; int n; int* off; int* cur; float* inv;
    if (blockIdx.x == 0) { deg = udeg; n = nu; off = uoff; cur = ucur; inv = uinv; }
    else                 { deg = sdeg; n = ns; off = soff; cur = scur; inv = sinv; }

    __shared__ int ssum[1024];
    int t = threadIdx.x;
    const int T = 1024;
    int chunk = (n + T - 1) / T;
    int lo = t * chunk;
    int hi = min(n, lo + chunk);

    int sum = 0;
    for (int i = lo; i < hi; i++) sum += deg[i];
    ssum[t] = sum;
    __syncthreads();

    // Hillis-Steele inclusive scan over the 1024 partial sums.
    for (int d = 1; d < T; d <<= 1) {
        int v = (t >= d) ? ssum[t - d] : 0;
        __syncthreads();
        ssum[t] += v;
        __syncthreads();
    }
    int run = ssum[t] - sum;   // exclusive prefix for this thread's chunk

    for (int i = lo; i < hi; i++) {
        int d = deg[i];
        off[i] = run;
        cur[i] = run;
        inv[i] = rsqrtf(d > 0 ? (float)d : 1e-6f);
        run += d;
    }
    if (hi == n && lo < n) off[n] = run;       // last non-empty chunk writes total
    if (n == 0 && t == 0)  off[0] = 0;
}

// ---------------------------------------------------------------------------
// K4: fill adjacency lists with the OPPOSITE endpoint.
// ---------------------------------------------------------------------------
__global__ void fill_kernel(const int* __restrict__ user_idx,
                            const int* __restrict__ spot_idx,
                            int n_edges,
                            int* __restrict__ ucur, int* __restrict__ uadj,
                            int* __restrict__ scur, int* __restrict__ sadj) {
    int stride = gridDim.x * blockDim.x;
    for (int e = blockIdx.x * blockDim.x + threadIdx.x; e < n_edges; e += stride) {
        int u = user_idx[e];
        int s = spot_idx[e];
        int p = atomicAdd(&ucur[u], 1);
        uadj[p] = s;
        int q = atomicAdd(&scur[s], 1);
        sadj[q] = u;
    }
}

// ---------------------------------------------------------------------------
// K5: pull-gather. Warp per destination node; lane = float2 column pair.
//   out[node] = inv_dst[node] * sum_{nb in adj(node)} x[nb] * inv_src[nb]
// Neighbor indices loaded 32-wide (coalesced) then broadcast via shuffle.
// ---------------------------------------------------------------------------
__global__ void gather_kernel(const float* __restrict__ x,
                              const int* __restrict__ adj,
                              const int* __restrict__ off,
                              const float* __restrict__ inv_src,
                              const float* __restrict__ inv_dst,
                              float* __restrict__ out,
                              int n_nodes) {
    int warp  = (blockIdx.x * blockDim.x + threadIdx.x) >> 5;
    int lane  = threadIdx.x & 31;
    int nwarp = (gridDim.x * blockDim.x) >> 5;
    int col   = lane * 2;

    for (int node = warp; node < n_nodes; node += nwarp) {
        int beg = off[node];
        int end = off[node + 1];
        float accx = 0.0f, accy = 0.0f;

        int base = beg;
        // full batches of 32 neighbors
        for (; base + 32 <= end; base += 32) {
            int   nb = adj[base + lane];
            float wv = __ldg(&inv_src[nb]);
            #pragma unroll 8
            for (int k = 0; k < 32; k++) {
                int   s  = __shfl_sync(0xffffffff, nb, k);
                float ws = __shfl_sync(0xffffffff, wv, k);
                float2 v = *reinterpret_cast<const float2*>(x + (size_t)s * FEAT + col);
                accx += v.x * ws;
                accy += v.y * ws;
            }
        }
        // remainder
        int rem = end - base;
        if (rem > 0) {
            int   nb = 0;
            float wv = 0.0f;
            if (lane < rem) {
                nb = adj[base + lane];
                wv = __ldg(&inv_src[nb]);
            }
            for (int k = 0; k < rem; k++) {
                int   s  = __shfl_sync(0xffffffff, nb, k);
                float ws = __shfl_sync(0xffffffff, wv, k);
                float2 v = *reinterpret_cast<const float2*>(x + (size_t)s * FEAT + col);
                accx += v.x * ws;
                accy += v.y * ws;
            }
        }

        float wd = __ldg(&inv_dst[node]);
        *reinterpret_cast<float2*>(out + (size_t)node * FEAT + col) =
            make_float2(accx * wd, accy * wd);
    }
}

// ---------------------------------------------------------------------------
extern "C" void kernel_launch(void* const* d_in, const int* in_sizes, int n_in,
                              void* d_out, int out_size) {
    const float* user_x   = (const float*)d_in[0];
    const float* spot_x   = (const float*)d_in[1];
    const int*   user_idx = (const int*)d_in[2];
    const int*   spot_idx = (const int*)d_in[3];

    int n_users = in_sizes[0] / FEAT;
    int n_spots = in_sizes[1] / FEAT;
    int n_edges = in_sizes[2];

    float* out      = (float*)d_out;
    float* user_out = out;
    float* spot_out = out + (size_t)n_users * FEAT;

    int *udeg, *sdeg, *uoff, *soff, *ucur, *scur, *uadj, *sadj;
    float *uinv, *sinv;
    cudaGetSymbolAddress((void**)&udeg, g_udeg);
    cudaGetSymbolAddress((void**)&sdeg, g_sdeg);
    cudaGetSymbolAddress((void**)&uoff, g_uoff);
    cudaGetSymbolAddress((void**)&soff, g_soff);
    cudaGetSymbolAddress((void**)&ucur, g_ucur);
    cudaGetSymbolAddress((void**)&scur, g_scur);
    cudaGetSymbolAddress((void**)&uinv, g_uinv);
    cudaGetSymbolAddress((void**)&sinv, g_sinv);
    cudaGetSymbolAddress((void**)&uadj, g_uadj);
    cudaGetSymbolAddress((void**)&sadj, g_sadj);

    const int TPB = 256;
    const int BLK = 148 * 8;

    zero_deg_kernel<<<BLK, TPB>>>(udeg, n_users, sdeg, n_spots);
    degree_kernel<<<BLK, TPB>>>(user_idx, spot_idx, n_edges, udeg, sdeg);
    scan_kernel<<<2, 1024>>>(udeg, n_users, uoff, ucur, uinv,
                             sdeg, n_spots, soff, scur, sinv);
    fill_kernel<<<BLK, TPB>>>(user_idx, spot_idx, n_edges, ucur, uadj, scur, sadj);

    // warp per node
    int ublocks = (n_users * 32 + TPB - 1) / TPB;
    int sblocks = (n_spots * 32 + TPB - 1) / TPB;
    gather_kernel<<<ublocks, TPB>>>(spot_x, uadj, uoff, sinv, uinv, user_out, n_users);
    gather_kernel<<<sblocks, TPB>>>(user_x, sadj, soff, uinv, sinv, spot_out, n_spots);
}

// round 3
// speedup vs baseline: 1.0002x; 1.0002x over previous
#include <cuda_runtime.h>
#include <cuda_bf16.h>

#define FEAT 64
#define MAX_USERS 200000
#define MAX_SPOTS 50000
#define MAX_EDGES 3200000

// ---- device scratch (no allocations allowed) ------------------------------
__device__ int   g_udeg[MAX_USERS];
__device__ int   g_sdeg[MAX_SPOTS];
__device__ int   g_uoff[MAX_USERS + 1];
__device__ int   g_soff[MAX_SPOTS + 1];
__device__ int   g_ucur[MAX_USERS];
__device__ int   g_scur[MAX_SPOTS];
__device__ float g_uinv[MAX_USERS];
__device__ float g_sinv[MAX_SPOTS];
__device__ int   g_uadj[MAX_EDGES];   // per-user list of spot neighbors
__device__ int   g_sadj[MAX_EDGES];   // per-spot list of user neighbors

// ---------------------------------------------------------------------------
// K1: zero the integer degree arrays.
// ---------------------------------------------------------------------------
__global__ void zero_deg_kernel(int* __restrict__ udeg, int nu,
                                int* __restrict__ sdeg, int ns) {
    int stride = gridDim.x * blockDim.x;
    for (int i = blockIdx.x * blockDim.x + threadIdx.x; i < nu; i += stride)
        udeg[i] = 0;
    for (int i = blockIdx.x * blockDim.x + threadIdx.x; i < ns; i += stride)
        sdeg[i] = 0;
}

// ---------------------------------------------------------------------------
// K2: integer degree counts. int4 loads, 8 independent atomics per iter.
// ---------------------------------------------------------------------------
__global__ void degree_kernel(const int* __restrict__ user_idx,
                              const int* __restrict__ spot_idx,
                              int n_edges,
                              int* __restrict__ udeg,
                              int* __restrict__ sdeg) {
    int tid    = blockIdx.x * blockDim.x + threadIdx.x;
    int stride = gridDim.x * blockDim.x;
    int nvec   = n_edges >> 2;

    const int4* u4 = (const int4*)user_idx;
    const int4* s4 = (const int4*)spot_idx;

    for (int i = tid; i < nvec; i += stride) {
        int4 u = u4[i];
        int4 s = s4[i];
        atomicAdd(&udeg[u.x], 1); atomicAdd(&udeg[u.y], 1);
        atomicAdd(&udeg[u.z], 1); atomicAdd(&udeg[u.w], 1);
        atomicAdd(&sdeg[s.x], 1); atomicAdd(&sdeg[s.y], 1);
        atomicAdd(&sdeg[s.z], 1); atomicAdd(&sdeg[s.w], 1);
    }
    // remainder
    for (int e = (nvec << 2) + tid; e < n_edges; e += stride) {
        atomicAdd(&udeg[user_idx[e]], 1);
        atomicAdd(&sdeg[spot_idx[e]], 1);
    }
}

// ---------------------------------------------------------------------------
// K3: exclusive scan of degrees -> offsets (+cursors) and inv_sqrt weights.
// Block 0 = users, block 1 = spots. 1024 threads each.
// ---------------------------------------------------------------------------
__global__ void scan_kernel(const int* __restrict__ udeg, int nu,
                            int* __restrict__ uoff, int* __restrict__ ucur,
                            float* __restrict__ uinv,
                            const int* __restrict__ sdeg, int ns,
                            int* __restrict__ soff, int* __restrict__ scur,
                            float* __restrict__ sinv) {
    const int* deg; int n; int* off; int* cur; float* inv;
    if (blockIdx.x == 0) { deg = udeg; n = nu; off = uoff; cur = ucur; inv = uinv; }
    else                 { deg = sdeg; n = ns; off = soff; cur = scur; inv = sinv; }

    __shared__ int ssum[1024];
    int t = threadIdx.x;
    const int T = 1024;
    int chunk = (n + T - 1) / T;
    int lo = t * chunk;
    int hi = min(n, lo + chunk);

    int sum = 0;
    for (int i = lo; i < hi; i++) sum += deg[i];
    ssum[t] = sum;
    __syncthreads();

    for (int d = 1; d < T; d <<= 1) {
        int v = (t >= d) ? ssum[t - d] : 0;
        __syncthreads();
        ssum[t] += v;
        __syncthreads();
    }
    int run = ssum[t] - sum;   // exclusive prefix for this thread's chunk

    for (int i = lo; i < hi; i++) {
        int d = deg[i];
        off[i] = run;
        cur[i] = run;
        inv[i] = rsqrtf(d > 0 ? (float)d : 1e-6f);
        run += d;
    }
    if (hi == n && lo < n) off[n] = run;
    if (n == 0 && t == 0)  off[0] = 0;
}

// ---------------------------------------------------------------------------
// K4: fill adjacency lists with the OPPOSITE endpoint.
// int4 loads; 8 independent cursor atomics per iteration for MLP.
// ---------------------------------------------------------------------------
__global__ void fill_kernel(const int* __restrict__ user_idx,
                            const int* __restrict__ spot_idx,
                            int n_edges,
                            int* __restrict__ ucur, int* __restrict__ uadj,
                            int* __restrict__ scur, int* __restrict__ sadj) {
    int tid    = blockIdx.x * blockDim.x + threadIdx.x;
    int stride = gridDim.x * blockDim.x;
    int nvec   = n_edges >> 2;

    const int4* u4 = (const int4*)user_idx;
    const int4* s4 = (const int4*)spot_idx;

    for (int i = tid; i < nvec; i += stride) {
        int4 u = u4[i];
        int4 s = s4[i];
        int p0 = atomicAdd(&ucur[u.x], 1);
        int p1 = atomicAdd(&ucur[u.y], 1);
        int p2 = atomicAdd(&ucur[u.z], 1);
        int p3 = atomicAdd(&ucur[u.w], 1);
        int q0 = atomicAdd(&scur[s.x], 1);
        int q1 = atomicAdd(&scur[s.y], 1);
        int q2 = atomicAdd(&scur[s.z], 1);
        int q3 = atomicAdd(&scur[s.w], 1);
        uadj[p0] = s.x; uadj[p1] = s.y; uadj[p2] = s.z; uadj[p3] = s.w;
        sadj[q0] = u.x; sadj[q1] = u.y; sadj[q2] = u.z; sadj[q3] = u.w;
    }
    for (int e = (nvec << 2) + tid; e < n_edges; e += stride) {
        int u = user_idx[e];
        int s = spot_idx[e];
        int p = atomicAdd(&ucur[u], 1);
        uadj[p] = s;
        int q = atomicAdd(&scur[s], 1);
        sadj[q] = u;
    }
}

// ---------------------------------------------------------------------------
// K5: pull-gather. Warp per destination node; lane = float2 column pair.
// Neighbor index is warp-uniform -> all lanes load same address (L1
// broadcast). Unroll x8 with batched prefetch of indices+weights; remainder
// handled by one predicated unroll-8 batch. No shuffles anywhere.
// ---------------------------------------------------------------------------
__global__ void gather_kernel(const float* __restrict__ x,
                              const int* __restrict__ adj,
                              const int* __restrict__ off,
                              const float* __restrict__ inv_src,
                              const float* __restrict__ inv_dst,
                              float* __restrict__ out,
                              int n_nodes) {
    int gwarp = (blockIdx.x * blockDim.x + threadIdx.x) >> 5;
    int lane  = threadIdx.x & 31;
    int col   = lane * 2;

    if (gwarp >= n_nodes) return;
    int node = gwarp;

    int beg = off[node];
    int end = off[node + 1];
    float wd = __ldg(&inv_dst[node]);

    float ax = 0.0f, ay = 0.0f;

    int cnt   = end - beg;
    int nfull = cnt & ~7;
    int j     = beg;

    for (; j < beg + nfull; j += 8) {
        int nb[8];
        float w[8];
        #pragma unroll
        for (int k = 0; k < 8; k++) nb[k] = __ldg(&adj[j + k]);
        #pragma unroll
        for (int k = 0; k < 8; k++) w[k] = __ldg(&inv_src[nb[k]]);
        #pragma unroll
        for (int k = 0; k < 8; k++) {
            float2 v = *reinterpret_cast<const float2*>(x + (size_t)nb[k] * FEAT + col);
            ax += v.x * w[k];
            ay += v.y * w[k];
        }
    }

    if (j < end) {
        int nb[8];
        float w[8];
        #pragma unroll
        for (int k = 0; k < 8; k++) {
            bool ok = (j + k) < end;
            nb[k] = ok ? __ldg(&adj[j + k]) : 0;
            w[k]  = ok ? __ldg(&inv_src[nb[k]]) : 0.0f;
        }
        #pragma unroll
        for (int k = 0; k < 8; k++) {
            float2 v = *reinterpret_cast<const float2*>(x + (size_t)nb[k] * FEAT + col);
            ax += v.x * w[k];
            ay += v.y * w[k];
        }
    }

    *reinterpret_cast<float2*>(out + (size_t)node * FEAT + col) =
        make_float2(ax * wd, ay * wd);
}

// ---------------------------------------------------------------------------
extern "C" void kernel_launch(void* const* d_in, const int* in_sizes, int n_in,
                              void* d_out, int out_size) {
    const float* user_x   = (const float*)d_in[0];
    const float* spot_x   = (const float*)d_in[1];
    const int*   user_idx = (const int*)d_in[2];
    const int*   spot_idx = (const int*)d_in[3];

    int n_users = in_sizes[0] / FEAT;
    int n_spots = in_sizes[1] / FEAT;
    int n_edges = in_sizes[2];

    float* out      = (float*)d_out;
    float* user_out = out;
    float* spot_out = out + (size_t)n_users * FEAT;

    int *udeg, *sdeg, *uoff, *soff, *ucur, *scur, *uadj, *sadj;
    float *uinv, *sinv;
    cudaGetSymbolAddress((void**)&udeg, g_udeg);
    cudaGetSymbolAddress((void**)&sdeg, g_sdeg);
    cudaGetSymbolAddress((void**)&uoff, g_uoff);
    cudaGetSymbolAddress((void**)&soff, g_soff);
    cudaGetSymbolAddress((void**)&ucur, g_ucur);
    cudaGetSymbolAddress((void**)&scur, g_scur);
    cudaGetSymbolAddress((void**)&uinv, g_uinv);
    cudaGetSymbolAddress((void**)&sinv, g_sinv);
    cudaGetSymbolAddress((void**)&uadj, g_uadj);
    cudaGetSymbolAddress((void**)&sadj, g_sadj);

    const int TPB = 256;
    const int BLK = 148 * 8;

    zero_deg_kernel<<<BLK, TPB>>>(udeg, n_users, sdeg, n_spots);
    degree_kernel<<<BLK, TPB>>>(user_idx, spot_idx, n_edges, udeg, sdeg);
    scan_kernel<<<2, 1024>>>(udeg, n_users, uoff, ucur, uinv,
                             sdeg, n_spots, soff, scur, sinv);
    fill_kernel<<<BLK, TPB>>>(user_idx, spot_idx, n_edges, ucur, uadj, scur, sadj);

    // warp per node, exact grids
    int ublocks = (n_users * 32 + TPB - 1) / TPB;
    int sblocks = (n_spots * 32 + TPB - 1) / TPB;
    gather_kernel<<<ublocks, TPB>>>(spot_x, uadj, uoff, sinv, uinv, user_out, n_users);
    gather_kernel<<<sblocks, TPB>>>(user_x, sadj, soff, uinv, sinv, spot_out, n_spots);
}

// round 4
// speedup vs baseline: 1.7876x; 1.7873x over previous
#include <cuda_runtime.h>
#include <cuda_bf16.h>

#define FEAT 64
#define MAX_USERS 200000
#define MAX_SPOTS 50000

__device__ int   g_udeg[MAX_USERS];
__device__ int   g_sdeg[MAX_SPOTS];
__device__ float g_uinv[MAX_USERS];
__device__ float g_sinv[MAX_SPOTS];

// ---------------------------------------------------------------------------
// K1: zero output (float4) and degree scratch.
// ---------------------------------------------------------------------------
__global__ void zero_kernel(float4* __restrict__ out4, int n4,
                            int* __restrict__ udeg, int nu,
                            int* __restrict__ sdeg, int ns) {
    int stride = gridDim.x * blockDim.x;
    int tid = blockIdx.x * blockDim.x + threadIdx.x;
    float4 z = make_float4(0.f, 0.f, 0.f, 0.f);
    for (int i = tid; i < n4; i += stride) out4[i] = z;
    for (int i = tid; i < nu; i += stride) udeg[i] = 0;
    for (int i = tid; i < ns; i += stride) sdeg[i] = 0;
}

// ---------------------------------------------------------------------------
// K2: integer degree counts, int4-batched (8 independent no-return atomics).
// ---------------------------------------------------------------------------
__global__ void degree_kernel(const int* __restrict__ user_idx,
                              const int* __restrict__ spot_idx,
                              int n_edges,
                              int* __restrict__ udeg,
                              int* __restrict__ sdeg) {
    int tid    = blockIdx.x * blockDim.x + threadIdx.x;
    int stride = gridDim.x * blockDim.x;
    int nvec   = n_edges >> 2;
    const int4* u4 = (const int4*)user_idx;
    const int4* s4 = (const int4*)spot_idx;
    for (int i = tid; i < nvec; i += stride) {
        int4 u = u4[i];
        int4 s = s4[i];
        atomicAdd(&udeg[u.x], 1); atomicAdd(&udeg[u.y], 1);
        atomicAdd(&udeg[u.z], 1); atomicAdd(&udeg[u.w], 1);
        atomicAdd(&sdeg[s.x], 1); atomicAdd(&sdeg[s.y], 1);
        atomicAdd(&sdeg[s.z], 1); atomicAdd(&sdeg[s.w], 1);
    }
    for (int e = (nvec << 2) + tid; e < n_edges; e += stride) {
        atomicAdd(&udeg[user_idx[e]], 1);
        atomicAdd(&sdeg[spot_idx[e]], 1);
    }
}

// ---------------------------------------------------------------------------
// K3: degree -> rsqrt weight.
// ---------------------------------------------------------------------------
__global__ void rsqrt_kernel(const int* __restrict__ udeg, float* __restrict__ uinv, int nu,
                             const int* __restrict__ sdeg, float* __restrict__ sinv, int ns) {
    int stride = gridDim.x * blockDim.x;
    int tid = blockIdx.x * blockDim.x + threadIdx.x;
    for (int i = tid; i < nu; i += stride) {
        int d = udeg[i];
        uinv[i] = rsqrtf(d > 0 ? (float)d : 1e-6f);
    }
    for (int i = tid; i < ns; i += stride) {
        int d = sdeg[i];
        sinv[i] = rsqrtf(d > 0 ? (float)d : 1e-6f);
    }
}

// ---------------------------------------------------------------------------
// Vector atomic: red.global.add.v4.f32 (sm_90+), fire-and-forget.
// ---------------------------------------------------------------------------
__device__ __forceinline__ void red_add_v4(float* p, float4 v) {
    asm volatile("red.global.add.v4.f32 [%0], {%1, %2, %3, %4};"
                 :: "l"(p), "f"(v.x), "f"(v.y), "f"(v.z), "f"(v.w)
                 : "memory");
}

// ---------------------------------------------------------------------------
// K4: main scatter. Half-warp per edge; lane = float4 column quarter.
// 2 edges in flight per warp; vector REDG.128 atomics (half the lane-ops
// of the float2 version for the same bytes).
// ---------------------------------------------------------------------------
__global__ void scatter_kernel(const float* __restrict__ user_x,
                               const float* __restrict__ spot_x,
                               const int* __restrict__ user_idx,
                               const int* __restrict__ spot_idx,
                               const float* __restrict__ uinv,
                               const float* __restrict__ sinv,
                               float* __restrict__ user_out,
                               float* __restrict__ spot_out,
                               int n_edges) {
    int gtid   = blockIdx.x * blockDim.x + threadIdx.x;
    int warp   = gtid >> 5;
    int lane   = threadIdx.x & 31;
    int half   = lane >> 4;          // which edge of the pair
    int hl     = lane & 15;          // lane within half-warp
    int col    = hl * 4;
    int nwarp  = (gridDim.x * blockDim.x) >> 5;
    int stride = nwarp * 2;

    for (int e = warp * 2 + half; e < n_edges; e += stride) {
        int u = __ldg(&user_idx[e]);     // uniform within half-warp
        int s = __ldg(&spot_idx[e]);
        float wu = __ldg(&uinv[u]);
        float ws = __ldg(&sinv[s]);

        float4 sx = *reinterpret_cast<const float4*>(spot_x + (size_t)s * FEAT + col);
        float4 ux = *reinterpret_cast<const float4*>(user_x + (size_t)u * FEAT + col);

        float4 to_user = make_float4(sx.x * ws, sx.y * ws, sx.z * ws, sx.w * ws);
        float4 to_spot = make_float4(ux.x * wu, ux.y * wu, ux.z * wu, ux.w * wu);

        red_add_v4(user_out + (size_t)u * FEAT + col, to_user);
        red_add_v4(spot_out + (size_t)s * FEAT + col, to_spot);
    }
}

// ---------------------------------------------------------------------------
// K5: post-normalize by destination inv_sqrt degree (float4).
// ---------------------------------------------------------------------------
__global__ void scale_kernel(float4* __restrict__ user_out4, int nu4,
                             float4* __restrict__ spot_out4, int ns4,
                             const float* __restrict__ uinv,
                             const float* __restrict__ sinv) {
    int stride = gridDim.x * blockDim.x;
    int tid = blockIdx.x * blockDim.x + threadIdx.x;
    // 16 float4 per row of 64 floats
    for (int i = tid; i < nu4; i += stride) {
        float w = uinv[i >> 4];
        float4 v = user_out4[i];
        user_out4[i] = make_float4(v.x * w, v.y * w, v.z * w, v.w * w);
    }
    for (int i = tid; i < ns4; i += stride) {
        float w = sinv[i >> 4];
        float4 v = spot_out4[i];
        spot_out4[i] = make_float4(v.x * w, v.y * w, v.z * w, v.w * w);
    }
}

// ---------------------------------------------------------------------------
extern "C" void kernel_launch(void* const* d_in, const int* in_sizes, int n_in,
                              void* d_out, int out_size) {
    const float* user_x   = (const float*)d_in[0];
    const float* spot_x   = (const float*)d_in[1];
    const int*   user_idx = (const int*)d_in[2];
    const int*   spot_idx = (const int*)d_in[3];

    int n_users = in_sizes[0] / FEAT;
    int n_spots = in_sizes[1] / FEAT;
    int n_edges = in_sizes[2];

    float* out      = (float*)d_out;
    float* user_out = out;
    float* spot_out = out + (size_t)n_users * FEAT;

    int *udeg, *sdeg;
    float *uinv, *sinv;
    cudaGetSymbolAddress((void**)&udeg, g_udeg);
    cudaGetSymbolAddress((void**)&sdeg, g_sdeg);
    cudaGetSymbolAddress((void**)&uinv, g_uinv);
    cudaGetSymbolAddress((void**)&sinv, g_sinv);

    const int TPB = 256;
    const int BLK = 148 * 8;

    zero_kernel<<<BLK, TPB>>>((float4*)out, out_size / 4, udeg, n_users, sdeg, n_spots);
    degree_kernel<<<BLK, TPB>>>(user_idx, spot_idx, n_edges, udeg, sdeg);
    rsqrt_kernel<<<BLK, TPB>>>(udeg, uinv, n_users, sdeg, sinv, n_spots);
    scatter_kernel<<<148 * 16, TPB>>>(user_x, spot_x, user_idx, spot_idx,
                                      uinv, sinv, user_out, spot_out, n_edges);
    scale_kernel<<<BLK, TPB>>>((float4*)user_out, n_users * FEAT / 4,
                               (float4*)spot_out, n_spots * FEAT / 4,
                               uinv, sinv);
}